// round 5
// baseline (speedup 1.0000x reference)
#include <cuda_runtime.h>
#include <cstdint>

// Sparsemax over rows of 16384 x 4096 fp32.
// Persistent CTAs; next row prefetched via cp.async into a shared double
// buffer. Sort-free exact tau via Michelot fixed point on a candidate
// superset gathered with PER-WARP thresholds (warpmax - 1) -- no block-wide
// max reduction needed, since any superset of the support converges to the
// exact tau. Full-row fallback if the candidate buffer overflows.

#define N_COLS      4096
#define THREADS     256
#define CAND_CAP    1024
#define CTAS_PER_SM 6
#define NBLOCKS     (152 * CTAS_PER_SM)   // one persistent wave on GB300

__global__ __launch_bounds__(THREADS, CTAS_PER_SM)
void sparsemax_kernel(const float* __restrict__ x, float* __restrict__ out,
                      int rows) {
    __shared__ float buf[2][N_COLS];     // 32 KB double buffer
    __shared__ float cand[CAND_CAP];     // 4 KB
    __shared__ float sh_tau;
    __shared__ int   sh_cnt;

    const int tid    = threadIdx.x;
    const int lane   = tid & 31;
    const int wid    = tid >> 5;
    const int stride = gridDim.x;

    // ---- prologue: prefetch first row ----
    int r0 = blockIdx.x;
    if (r0 < rows) {
        const float4* g = reinterpret_cast<const float4*>(x + (size_t)r0 * N_COLS);
        uint32_t s = (uint32_t)__cvta_generic_to_shared(&buf[0][0]);
#pragma unroll
        for (int k = 0; k < 4; k++) {
            uint32_t saddr = s + (uint32_t)(tid + k * THREADS) * 16u;
            asm volatile("cp.async.cg.shared.global [%0], [%1], 16;\n"
                         :: "r"(saddr), "l"(g + tid + k * THREADS));
        }
    }
    asm volatile("cp.async.commit_group;\n" ::: "memory");

    int p = 0;
    for (int r = r0; r < rows; r += stride, p ^= 1) {
        // ---- prefetch next row into buf[p^1] (overlaps this row's tau) ----
        const int rn = r + stride;
        if (rn < rows) {
            const float4* g = reinterpret_cast<const float4*>(x + (size_t)rn * N_COLS);
            uint32_t s = (uint32_t)__cvta_generic_to_shared(&buf[p ^ 1][0]);
#pragma unroll
            for (int k = 0; k < 4; k++) {
                uint32_t saddr = s + (uint32_t)(tid + k * THREADS) * 16u;
                asm volatile("cp.async.cg.shared.global [%0], [%1], 16;\n"
                             :: "r"(saddr), "l"(g + tid + k * THREADS));
            }
        }
        asm volatile("cp.async.commit_group;\n" ::: "memory");

        if (tid == 0) sh_cnt = 0;

        // wait for buf[p] (older group), leave the prefetch in flight
        asm volatile("cp.async.wait_group 1;\n" ::: "memory");
        __syncthreads();                                     // B1

        const float4* b = reinterpret_cast<const float4*>(&buf[p][0]);

        // ---- fused pass: per-warp max, then gather x > warpmax-1 ----
        // (support ⊆ {x > rowmax-1} ⊆ {x > warpmax(w)-1} per element's warp,
        //  so the union over warps is a valid Michelot starting superset)
        float4 v[4];
        float m = -3.402823466e38f;
#pragma unroll
        for (int k = 0; k < 4; k++) {
            v[k] = b[tid + k * THREADS];
            m = fmaxf(m, fmaxf(fmaxf(v[k].x, v[k].y), fmaxf(v[k].z, v[k].w)));
        }
#pragma unroll
        for (int o = 16; o > 0; o >>= 1)
            m = fmaxf(m, __shfl_xor_sync(0xffffffffu, m, o));
        const float wthresh = m - 1.0f;

#pragma unroll
        for (int k = 0; k < 4; k++) {
            float vals[4] = {v[k].x, v[k].y, v[k].z, v[k].w};
#pragma unroll
            for (int j = 0; j < 4; j++) {
                if (vals[j] > wthresh) {
                    int q = atomicAdd(&sh_cnt, 1);
                    if (q < CAND_CAP) cand[q] = vals[j];
                }
            }
        }
        __syncthreads();                                     // B2

        // ---- warp 0: Michelot fixed point (exact); full-row fallback ----
        if (wid == 0) {
            int n = sh_cnt;
            const float* src = cand;
            if (n > CAND_CAP) { n = N_COLS; src = &buf[p][0]; }  // rare, exact
            float t = -3.402823466e38f;   // start with full candidate set
            int c_prev = -1;
            for (;;) {
                float s = 0.0f;
                int   c = 0;
                for (int i = lane; i < n; i += 32) {
                    float z = src[i];
                    if (z > t) { s += z; c++; }
                }
#pragma unroll
                for (int o = 16; o > 0; o >>= 1) {
                    s += __shfl_xor_sync(0xffffffffu, s, o);
                    c += __shfl_xor_sync(0xffffffffu, c, o);
                }
                if (c == c_prev) break;        // support stabilized -> exact tau
                t = (s - 1.0f) / (float)c;     // c >= 1 (max element in support)
                c_prev = c;
            }
            if (lane == 0) sh_tau = t;
        }
        __syncthreads();                                     // B3
        const float tau = sh_tau;

        // ---- output pass: write max(x - tau, 0), streaming stores ----
        float4* orow = reinterpret_cast<float4*>(out + (size_t)r * N_COLS);
#pragma unroll
        for (int k = 0; k < 4; k++) {
            float4 w = b[tid + k * THREADS];
            float4 o;
            o.x = fmaxf(w.x - tau, 0.0f);
            o.y = fmaxf(w.y - tau, 0.0f);
            o.z = fmaxf(w.z - tau, 0.0f);
            o.w = fmaxf(w.w - tau, 0.0f);
            __stcs(&orow[tid + k * THREADS], o);
        }
    }
}

extern "C" void kernel_launch(void* const* d_in, const int* in_sizes, int n_in,
                              void* d_out, int out_size) {
    const float* x = (const float*)d_in[0];
    float* out = (float*)d_out;
    const int rows = in_sizes[0] / N_COLS;   // 16384
    sparsemax_kernel<<<NBLOCKS, THREADS>>>(x, out, rows);
}

// round 6
// speedup vs baseline: 1.2335x; 1.2335x over previous
#include <cuda_runtime.h>
#include <cstdint>

// Sparsemax over rows of 16384 x 4096 fp32.
// Persistent CTAs; next row prefetched via cp.async into a shared double
// buffer. Exact sort-free tau: candidates {x > rowmax-1} (true support is
// always a subset) + Michelot fixed-point, run REDUNDANTLY by all warps so
// no broadcast barrier / idle warps. Full-row fallback on candidate
// overflow keeps correctness unconditional.
//
// Cross-iteration shared state (counters, candidate buffer) is recycled
// with parity double-buffering; every reset/写 is separated from the last
// read of the previous row by a full __syncthreads in between.

#define N_COLS      4096
#define THREADS     256
#define CAND_CAP    1024
#define CTAS_PER_SM 6
#define NBLOCKS     (152 * CTAS_PER_SM)   // one persistent wave on GB300

__device__ __forceinline__ unsigned enc_f(float f) {
    unsigned u = __float_as_uint(f);
    return (u & 0x80000000u) ? ~u : (u | 0x80000000u);   // order-preserving
}
__device__ __forceinline__ float dec_f(unsigned e) {
    unsigned u = (e & 0x80000000u) ? (e & 0x7fffffffu) : ~e;
    return __uint_as_float(u);
}

__global__ __launch_bounds__(THREADS, CTAS_PER_SM)
void sparsemax_kernel(const float* __restrict__ x, float* __restrict__ out,
                      int rows) {
    __shared__ float    buf[2][N_COLS];     // 32 KB double buffer
    __shared__ float    cand[CAND_CAP];     // 4 KB
    __shared__ unsigned sh_maxbits[2];      // parity-buffered
    __shared__ int      sh_cnt[2];          // parity-buffered

    const int tid    = threadIdx.x;
    const int stride = gridDim.x;

    // ---- prologue: init both counter slots, prefetch first row ----
    if (tid == 0) {
        sh_maxbits[0] = 0u; sh_maxbits[1] = 0u;
        sh_cnt[0] = 0;      sh_cnt[1] = 0;
    }
    int r0 = blockIdx.x;
    if (r0 < rows) {
        const float4* g = reinterpret_cast<const float4*>(x + (size_t)r0 * N_COLS);
        uint32_t s = (uint32_t)__cvta_generic_to_shared(&buf[0][0]);
#pragma unroll
        for (int k = 0; k < 4; k++) {
            uint32_t saddr = s + (uint32_t)(tid + k * THREADS) * 16u;
            asm volatile("cp.async.cg.shared.global [%0], [%1], 16;\n"
                         :: "r"(saddr), "l"(g + tid + k * THREADS));
        }
    }
    asm volatile("cp.async.commit_group;\n" ::: "memory");

    int p = 0;
    for (int r = r0; r < rows; r += stride, p ^= 1) {
        // ---- prefetch next row into buf[p^1] (overlaps this row's tau) ----
        const int rn = r + stride;
        if (rn < rows) {
            const float4* g = reinterpret_cast<const float4*>(x + (size_t)rn * N_COLS);
            uint32_t s = (uint32_t)__cvta_generic_to_shared(&buf[p ^ 1][0]);
#pragma unroll
            for (int k = 0; k < 4; k++) {
                uint32_t saddr = s + (uint32_t)(tid + k * THREADS) * 16u;
                asm volatile("cp.async.cg.shared.global [%0], [%1], 16;\n"
                             :: "r"(saddr), "l"(g + tid + k * THREADS));
            }
        }
        asm volatile("cp.async.commit_group;\n" ::: "memory");

        // wait for buf[p] (older group), leave the prefetch in flight
        asm volatile("cp.async.wait_group 1;\n" ::: "memory");
        __syncthreads();                                     // B1

        // reset the OTHER parity's slots for the next row: every reader of
        // slot p^1 (previous row) has passed B1, so this is race-free, and
        // the next row's users are ordered by their own B1.
        if (tid == 0) { sh_maxbits[p ^ 1] = 0u; sh_cnt[p ^ 1] = 0; }

        const float4* b = reinterpret_cast<const float4*>(&buf[p][0]);

        // ---- pass 1: row max (REDUX warp max + one shared atomicMax) ----
        float4 v[4];
        float m = -3.402823466e38f;
#pragma unroll
        for (int k = 0; k < 4; k++) {
            v[k] = b[tid + k * THREADS];
            m = fmaxf(m, fmaxf(fmaxf(v[k].x, v[k].y), fmaxf(v[k].z, v[k].w)));
        }
        unsigned we = __reduce_max_sync(0xffffffffu, enc_f(m));
        if ((tid & 31) == 0) atomicMax(&sh_maxbits[p], we);
        __syncthreads();                                     // B2

        const float thresh = dec_f(sh_maxbits[p]) - 1.0f;   // tau* >= thresh

        // ---- pass 2: gather candidates (x > rowmax - 1) ----
#pragma unroll
        for (int k = 0; k < 4; k++) {
            float vals[4] = {v[k].x, v[k].y, v[k].z, v[k].w};
#pragma unroll
            for (int j = 0; j < 4; j++) {
                if (vals[j] > thresh) {
                    int q = atomicAdd(&sh_cnt[p], 1);
                    if (q < CAND_CAP) cand[q] = vals[j];
                }
            }
        }
        __syncthreads();                                     // B3

        // ---- ALL warps: redundant Michelot fixed point (exact) ----
        // shfl/redux give every lane the converged tau -> no broadcast,
        // no barrier; each warp proceeds to its stores as soon as it's done.
        float tau;
        {
            int n = sh_cnt[p];
            const float* src = cand;
            if (n > CAND_CAP) { n = N_COLS; src = &buf[p][0]; }  // rare, exact
            const int lane = tid & 31;
            float t = thresh;
            int c_prev = -1;
            for (;;) {
                float s = 0.0f;
                int   c = 0;
                for (int i = lane; i < n; i += 32) {
                    float z = src[i];
                    if (z > t) { s += z; c++; }
                }
#pragma unroll
                for (int o = 16; o > 0; o >>= 1)
                    s += __shfl_xor_sync(0xffffffffu, s, o);
                c = __reduce_add_sync(0xffffffffu, c);
                if (c == c_prev) break;        // support stabilized -> exact tau
                t = (s - 1.0f) / (float)c;     // c >= 1 (rowmax in support)
                c_prev = c;
            }
            tau = t;
        }

        // ---- pass 3: write max(x - tau, 0), streaming stores ----
        float4* orow = reinterpret_cast<float4*>(out + (size_t)r * N_COLS);
#pragma unroll
        for (int k = 0; k < 4; k++) {
            float4 w = b[tid + k * THREADS];
            float4 o;
            o.x = fmaxf(w.x - tau, 0.0f);
            o.y = fmaxf(w.y - tau, 0.0f);
            o.z = fmaxf(w.z - tau, 0.0f);
            o.w = fmaxf(w.w - tau, 0.0f);
            __stcs(&orow[tid + k * THREADS], o);
        }
    }
}

extern "C" void kernel_launch(void* const* d_in, const int* in_sizes, int n_in,
                              void* d_out, int out_size) {
    const float* x = (const float*)d_in[0];
    float* out = (float*)d_out;
    const int rows = in_sizes[0] / N_COLS;   // 16384
    sparsemax_kernel<<<NBLOCKS, THREADS>>>(x, out, rows);
}